// round 3
// baseline (speedup 1.0000x reference)
#include <cuda_runtime.h>

#define EMAX 65536
#define GMAX 64

__device__ float g_x[(size_t)EMAX * 64];
__device__ float g_aggr[(size_t)EMAX * 64];
__device__ float g_deg[EMAX];
__device__ int   g_bt[EMAX];
__device__ float g_gsum[GMAX * 64];
__device__ float g_gcnt[GMAX];

typedef unsigned long long u64;

__device__ __forceinline__ u64 pack2(float x) {
    u64 r; asm("mov.b64 %0, {%1, %2};" : "=l"(r) : "f"(x), "f"(x)); return r;
}
__device__ __forceinline__ void unpack2(u64 v, float& lo, float& hi) {
    asm("mov.b64 {%0, %1}, %2;" : "=f"(lo), "=f"(hi) : "l"(v));
}
__device__ __forceinline__ float gethalf(u64 v, int which) {
    float lo, hi; unpack2(v, lo, hi); return which ? hi : lo;
}
__device__ __forceinline__ u64 ffma2(u64 a, u64 b, u64 c) {
    u64 d; asm("fma.rn.f32x2 %0, %1, %2, %3;" : "=l"(d) : "l"(a), "l"(b), "l"(c)); return d;
}
__device__ __forceinline__ float silu_f(float v) {
    return __fdividef(v, 1.f + __expf(-v));
}

__device__ __forceinline__ void cpys(float* dst, const float* __restrict__ src, int n) {
    const float4* s4 = (const float4*)src; float4* d4 = (float4*)dst;
    for (int i = threadIdx.x; i < (n >> 2); i += blockDim.x) d4[i] = s4[i];
}

// One 64-wide input segment: 2 edges, thread owns cols [8*oct, 8*oct+8).
// wso = weight smem base + segment offset + 8*oct; row stride 64, plain row-major.
template<bool SCALED>
__device__ __forceinline__ void gemv_seg2(
    const float* __restrict__ i0, const float* __restrict__ i1,
    const float* wso, u64 a0[4], u64 a1[4], float s0 = 1.f, float s1 = 1.f)
{
    const float4* p0 = (const float4*)i0;
    const float4* p1 = (const float4*)i1;
    #pragma unroll 4
    for (int kk = 0; kk < 16; kk++) {
        float4 v0 = p0[kk], v1 = p1[kk];
        if (SCALED) {
            v0.x *= s0; v0.y *= s0; v0.z *= s0; v0.w *= s0;
            v1.x *= s1; v1.y *= s1; v1.z *= s1; v1.w *= s1;
        }
        #pragma unroll
        for (int j = 0; j < 4; j++) {
            const float* wr = wso + (4 * kk + j) * 64;
            ulonglong2 w0 = *(const ulonglong2*)wr;
            ulonglong2 w1 = *(const ulonglong2*)(wr + 4);
            float f0 = (j == 0) ? v0.x : (j == 1) ? v0.y : (j == 2) ? v0.z : v0.w;
            float f1 = (j == 0) ? v1.x : (j == 1) ? v1.y : (j == 2) ? v1.z : v1.w;
            u64 q0 = pack2(f0), q1 = pack2(f1);
            a0[0] = ffma2(q0, w0.x, a0[0]); a0[1] = ffma2(q0, w0.y, a0[1]);
            a0[2] = ffma2(q0, w1.x, a0[2]); a0[3] = ffma2(q0, w1.y, a0[3]);
            a1[0] = ffma2(q1, w0.x, a1[0]); a1[1] = ffma2(q1, w0.y, a1[1]);
            a1[2] = ffma2(q1, w1.x, a1[2]); a1[3] = ffma2(q1, w1.y, a1[3]);
        }
    }
}

// Second GEMV 64->64, chunked hidden exchange through hst[32][64].
// w2so = w2 smem base + 8*oct.
__device__ __forceinline__ void gemv2_oct(
    const u64 a0[4], const u64 a1[4], const float* w2so,
    u64 o0[4], u64 o1[4], float* hst, int oct, int ebl)
{
    #pragma unroll
    for (int C = 0; C < 2; C++) {
        if ((oct >> 2) == C) {
            #pragma unroll
            for (int j = 0; j < 8; j++) {
                int kp = 8 * (oct & 3) + j;
                float2 sv;
                sv.x = silu_f(gethalf(a0[j >> 1], j & 1));
                sv.y = silu_f(gethalf(a1[j >> 1], j & 1));
                *(float2*)(hst + kp * 64 + ebl) = sv;
            }
        }
        __syncthreads();
        #pragma unroll 4
        for (int k = 0; k < 32; k++) {
            float2 hv = *(const float2*)(hst + k * 64 + ebl);
            const float* wr = w2so + (32 * C + k) * 64;
            ulonglong2 w0 = *(const ulonglong2*)wr;
            ulonglong2 w1 = *(const ulonglong2*)(wr + 4);
            u64 q0 = pack2(hv.x), q1 = pack2(hv.y);
            o0[0] = ffma2(q0, w0.x, o0[0]); o0[1] = ffma2(q0, w0.y, o0[1]);
            o0[2] = ffma2(q0, w1.x, o0[2]); o0[3] = ffma2(q0, w1.y, o0[3]);
            o1[0] = ffma2(q1, w0.x, o1[0]); o1[1] = ffma2(q1, w0.y, o1[1]);
            o1[2] = ffma2(q1, w1.x, o1[2]); o1[3] = ffma2(q1, w1.y, o1[3]);
        }
        __syncthreads();
    }
}

__device__ __forceinline__ void load_bias2(const float* bs, int oct, u64 a0[4], u64 a1[4]) {
    ulonglong2 t0 = *(const ulonglong2*)(bs + 8 * oct);
    ulonglong2 t1 = *(const ulonglong2*)(bs + 8 * oct + 4);
    a0[0] = t0.x; a0[1] = t0.y; a0[2] = t1.x; a0[3] = t1.y;
    a1[0] = t0.x; a1[1] = t0.y; a1[2] = t1.x; a1[3] = t1.y;
}

// ---------------- kernels ----------------

__global__ void k_zero_small(int E) {
    int i = blockIdx.x * blockDim.x + threadIdx.x;
    if (i < E) g_deg[i] = 0.f;
    if (i < GMAX * 64) g_gsum[i] = 0.f;
    if (i < GMAX) g_gcnt[i] = 0.f;
}

__global__ void k_zero_aggr(int n) {
    for (int i = blockIdx.x * blockDim.x + threadIdx.x; i < n; i += gridDim.x * blockDim.x)
        g_aggr[i] = 0.f;
}

extern "C" __global__ void __launch_bounds__(256, 2)
k_init(const float* __restrict__ af, const int* __restrict__ eidx,
       const float* __restrict__ iw1, const float* __restrict__ ib1,
       const float* __restrict__ iw2, const float* __restrict__ ib2, int E) {
    extern __shared__ float sm[];
    float* w1s = sm;             // 256*64 = 16384
    float* w2s = sm + 16384;     // 4096
    float* b1s = sm + 20480;     // 64
    float* b2s = sm + 20544;     // 64
    float* hst = sm + 20608;     // 32*64 = 2048
    cpys(w1s, iw1, 16384); cpys(w2s, iw2, 4096);
    if (threadIdx.x < 64) { b1s[threadIdx.x] = ib1[threadIdx.x]; b2s[threadIdx.x] = ib2[threadIdx.x]; }
    __syncthreads();

    int tid = threadIdx.x, lane = tid & 31, warp = tid >> 5;
    int oct = lane >> 2, gl = lane & 3;
    int ebl = warp * 8 + gl * 2;
    int e0 = blockIdx.x * 64 + ebl;
    bool v0 = e0 < E, v1 = e0 + 1 < E;
    int ec0 = v0 ? e0 : 0, ec1 = v1 ? e0 + 1 : 0;
    int r0 = eidx[ec0], c0 = eidx[E + ec0];
    int r1 = eidx[ec1], c1 = eidx[E + ec1];
    const float* hi0 = af + (size_t)r0 * 128;
    const float* hj0 = af + (size_t)c0 * 128;
    const float* hi1 = af + (size_t)r1 * 128;
    const float* hj1 = af + (size_t)c1 * 128;

    // cosine similarity: 8 lanes (oct=0..7) split 128 dims, shfl-reduce over oct bits
    float dot0 = 0.f, na0 = 0.f, nb0 = 0.f, dot1 = 0.f, na1 = 0.f, nb1 = 0.f;
    {
        const float4* A0 = (const float4*)hi0 + 4 * oct;
        const float4* B0 = (const float4*)hj0 + 4 * oct;
        const float4* A1 = (const float4*)hi1 + 4 * oct;
        const float4* B1 = (const float4*)hj1 + 4 * oct;
        #pragma unroll
        for (int t = 0; t < 4; t++) {
            float4 a = A0[t], b = B0[t];
            dot0 += a.x*b.x + a.y*b.y + a.z*b.z + a.w*b.w;
            na0  += a.x*a.x + a.y*a.y + a.z*a.z + a.w*a.w;
            nb0  += b.x*b.x + b.y*b.y + b.z*b.z + b.w*b.w;
            float4 c = A1[t], d = B1[t];
            dot1 += c.x*d.x + c.y*d.y + c.z*d.z + c.w*d.w;
            na1  += c.x*c.x + c.y*c.y + c.z*c.z + c.w*c.w;
            nb1  += d.x*d.x + d.y*d.y + d.z*d.z + d.w*d.w;
        }
    }
    #pragma unroll
    for (int m = 4; m <= 16; m <<= 1) {
        dot0 += __shfl_xor_sync(~0u, dot0, m); na0 += __shfl_xor_sync(~0u, na0, m);
        nb0  += __shfl_xor_sync(~0u, nb0, m);  dot1 += __shfl_xor_sync(~0u, dot1, m);
        na1  += __shfl_xor_sync(~0u, na1, m);  nb1 += __shfl_xor_sync(~0u, nb1, m);
    }
    if (oct == 0) {
        if (v0) {
            float a = fmaxf(sqrtf(na0), 1e-8f), b = fmaxf(sqrtf(nb0), 1e-8f);
            float sim = dot0 / (a * b);
            int bt = 0; if (sim > 0.8f) bt = 1; if (sim > 0.9f) bt = 2; if (sim < 0.3f) bt = 3;
            g_bt[e0] = bt;
        }
        if (v1) {
            float a = fmaxf(sqrtf(na1), 1e-8f), b = fmaxf(sqrtf(nb1), 1e-8f);
            float sim = dot1 / (a * b);
            int bt = 0; if (sim > 0.8f) bt = 1; if (sim > 0.9f) bt = 2; if (sim < 0.3f) bt = 3;
            g_bt[e0 + 1] = bt;
        }
    }

    const float* wso = w1s + 8 * oct;
    u64 a0[4], a1[4]; load_bias2(b1s, oct, a0, a1);
    gemv_seg2<false>(hi0,      hi1,      wso,             a0, a1);
    gemv_seg2<false>(hi0 + 64, hi1 + 64, wso + 64 * 64,   a0, a1);
    gemv_seg2<false>(hj0,      hj1,      wso + 128 * 64,  a0, a1);
    gemv_seg2<false>(hj0 + 64, hj1 + 64, wso + 192 * 64,  a0, a1);
    u64 o0[4], o1[4]; load_bias2(b2s, oct, o0, o1);
    gemv2_oct(a0, a1, w2s + 8 * oct, o0, o1, hst, oct, ebl);

    if (v0) {
        float* xp = g_x + (size_t)e0 * 64 + 8 * oct;
        float x0, x1, x2, x3;
        unpack2(o0[0], x0, x1); unpack2(o0[1], x2, x3);
        *(float4*)xp = make_float4(x0, x1, x2, x3);
        unpack2(o0[2], x0, x1); unpack2(o0[3], x2, x3);
        *(float4*)(xp + 4) = make_float4(x0, x1, x2, x3);
    }
    if (v1) {
        float* xp = g_x + (size_t)(e0 + 1) * 64 + 8 * oct;
        float x0, x1, x2, x3;
        unpack2(o1[0], x0, x1); unpack2(o1[1], x2, x3);
        *(float4*)xp = make_float4(x0, x1, x2, x3);
        unpack2(o1[2], x0, x1); unpack2(o1[3], x2, x3);
        *(float4*)(xp + 4) = make_float4(x0, x1, x2, x3);
    }
}

__global__ void k_deg(const int* __restrict__ bei, int BE) {
    int b = blockIdx.x * blockDim.x + threadIdx.x;
    if (b < BE) atomicAdd(&g_deg[bei[BE + b]], 1.f);
}

extern "C" __global__ void __launch_bounds__(256, 2)
k_msg(const int* __restrict__ bei, const float* __restrict__ embl,
      const float* __restrict__ mw1, const float* __restrict__ mb1,
      const float* __restrict__ mw2, const float* __restrict__ mb2, int BE) {
    extern __shared__ float sm[];
    float* w1s = sm;             // 12288
    float* w2s = sm + 12288;     // 4096
    float* b1s = sm + 16384;     // 64
    float* b2s = sm + 16448;     // 64
    float* hst = sm + 16512;     // 2048
    cpys(w1s, mw1, 12288); cpys(w2s, mw2, 4096);
    if (threadIdx.x < 64) { b1s[threadIdx.x] = mb1[threadIdx.x]; b2s[threadIdx.x] = mb2[threadIdx.x]; }
    __syncthreads();

    int tid = threadIdx.x, lane = tid & 31, warp = tid >> 5;
    int oct = lane >> 2, gl = lane & 3;
    int ebl = warp * 8 + gl * 2;
    int e0 = blockIdx.x * 64 + ebl;
    bool v0 = e0 < BE, v1 = e0 + 1 < BE;
    int ec0 = v0 ? e0 : 0, ec1 = v1 ? e0 + 1 : 0;
    int s0 = bei[ec0], d0 = bei[BE + ec0];
    int s1 = bei[ec1], d1 = bei[BE + ec1];

    const float* wso = w1s + 8 * oct;
    u64 a0[4], a1[4]; load_bias2(b1s, oct, a0, a1);
    gemv_seg2<false>(g_x + (size_t)d0 * 64, g_x + (size_t)d1 * 64, wso,           a0, a1);
    gemv_seg2<false>(g_x + (size_t)s0 * 64, g_x + (size_t)s1 * 64, wso + 64 * 64, a0, a1);
    gemv_seg2<false>(embl + g_bt[d0] * 64, embl + g_bt[d1] * 64, wso + 128 * 64,  a0, a1);
    u64 o0[4], o1[4]; load_bias2(b2s, oct, o0, o1);
    gemv2_oct(a0, a1, w2s + 8 * oct, o0, o1, hst, oct, ebl);

    if (v0) {
        float* ag = g_aggr + (size_t)d0 * 64 + 8 * oct;
        float x0, x1, x2, x3;
        unpack2(o0[0], x0, x1); unpack2(o0[1], x2, x3);
        asm volatile("red.global.add.v4.f32 [%0], {%1,%2,%3,%4};"
                     :: "l"(ag), "f"(x0), "f"(x1), "f"(x2), "f"(x3) : "memory");
        unpack2(o0[2], x0, x1); unpack2(o0[3], x2, x3);
        asm volatile("red.global.add.v4.f32 [%0], {%1,%2,%3,%4};"
                     :: "l"(ag + 4), "f"(x0), "f"(x1), "f"(x2), "f"(x3) : "memory");
    }
    if (v1) {
        float* ag = g_aggr + (size_t)d1 * 64 + 8 * oct;
        float x0, x1, x2, x3;
        unpack2(o1[0], x0, x1); unpack2(o1[1], x2, x3);
        asm volatile("red.global.add.v4.f32 [%0], {%1,%2,%3,%4};"
                     :: "l"(ag), "f"(x0), "f"(x1), "f"(x2), "f"(x3) : "memory");
        unpack2(o1[2], x0, x1); unpack2(o1[3], x2, x3);
        asm volatile("red.global.add.v4.f32 [%0], {%1,%2,%3,%4};"
                     :: "l"(ag + 4), "f"(x0), "f"(x1), "f"(x2), "f"(x3) : "memory");
    }
}

extern "C" __global__ void __launch_bounds__(256, 2)
k_upd(const float* __restrict__ uw1, const float* __restrict__ ub1,
      const float* __restrict__ uw2, const float* __restrict__ ub2, int E) {
    extern __shared__ float sm[];
    float* w1s = sm;             // 8192
    float* w2s = sm + 8192;      // 4096
    float* b1s = sm + 12288;     // 64
    float* b2s = sm + 12352;     // 64
    float* hst = sm + 12416;     // 2048
    cpys(w1s, uw1, 8192); cpys(w2s, uw2, 4096);
    if (threadIdx.x < 64) { b1s[threadIdx.x] = ub1[threadIdx.x]; b2s[threadIdx.x] = ub2[threadIdx.x]; }
    __syncthreads();

    int tid = threadIdx.x, lane = tid & 31, warp = tid >> 5;
    int oct = lane >> 2, gl = lane & 3;
    int ebl = warp * 8 + gl * 2;
    int e0 = blockIdx.x * 64 + ebl;
    bool v0 = e0 < E, v1 = e0 + 1 < E;
    int ec0 = v0 ? e0 : 0, ec1 = v1 ? e0 + 1 : 0;
    float rd0 = 1.f / fmaxf(g_deg[ec0], 1.f);
    float rd1 = 1.f / fmaxf(g_deg[ec1], 1.f);

    const float* wso = w1s + 8 * oct;
    u64 a0[4], a1[4]; load_bias2(b1s, oct, a0, a1);
    gemv_seg2<true>(g_aggr + (size_t)ec0 * 64, g_aggr + (size_t)ec1 * 64, wso, a0, a1, rd0, rd1);
    gemv_seg2<false>(g_x + (size_t)ec0 * 64, g_x + (size_t)ec1 * 64, wso + 64 * 64, a0, a1);
    u64 o0[4], o1[4]; load_bias2(b2s, oct, o0, o1);
    gemv2_oct(a0, a1, w2s + 8 * oct, o0, o1, hst, oct, ebl);

    if (v0) {
        float* xp = g_x + (size_t)e0 * 64 + 8 * oct;
        float4 xa = *(float4*)xp, xb = *(float4*)(xp + 4);
        float x0, x1, x2, x3;
        unpack2(o0[0], x0, x1); unpack2(o0[1], x2, x3);
        xa.x += x0; xa.y += x1; xa.z += x2; xa.w += x3;
        unpack2(o0[2], x0, x1); unpack2(o0[3], x2, x3);
        xb.x += x0; xb.y += x1; xb.z += x2; xb.w += x3;
        *(float4*)xp = xa; *(float4*)(xp + 4) = xb;
    }
    if (v1) {
        float* xp = g_x + (size_t)(e0 + 1) * 64 + 8 * oct;
        float4 xa = *(float4*)xp, xb = *(float4*)(xp + 4);
        float x0, x1, x2, x3;
        unpack2(o1[0], x0, x1); unpack2(o1[1], x2, x3);
        xa.x += x0; xa.y += x1; xa.z += x2; xa.w += x3;
        unpack2(o1[2], x0, x1); unpack2(o1[3], x2, x3);
        xb.x += x0; xb.y += x1; xb.z += x2; xb.w += x3;
        *(float4*)xp = xa; *(float4*)(xp + 4) = xb;
    }
}

__global__ void k_cnt(const int* __restrict__ eidx, const int* __restrict__ batch, int E) {
    int e = blockIdx.x * blockDim.x + threadIdx.x;
    if (e < E) atomicAdd(&g_gcnt[batch[eidx[e]]], 1.f);
}

__global__ void k_pool2(const int* __restrict__ eidx, const int* __restrict__ batch, int E) {
    int i = blockIdx.x * blockDim.x + threadIdx.x;
    if (i >= E * 16) return;
    int e = i >> 4, cc = i & 15;
    int gph = batch[eidx[e]];
    float4 v = ((const float4*)g_x)[(size_t)e * 16 + cc];
    float* dst = g_gsum + gph * 64 + cc * 4;
    asm volatile("red.global.add.v4.f32 [%0], {%1,%2,%3,%4};"
                 :: "l"(dst), "f"(v.x), "f"(v.y), "f"(v.z), "f"(v.w) : "memory");
}

__global__ void k_fin(float* __restrict__ out, int G) {
    int i = blockIdx.x * blockDim.x + threadIdx.x;
    if (i < G * 64) out[i] = g_gsum[i] / fmaxf(g_gcnt[i >> 6], 1.f);
}

__global__ void k_copy(float4* __restrict__ out, int n4) {
    const float4* src = (const float4*)g_x;
    for (int i = blockIdx.x * blockDim.x + threadIdx.x; i < n4; i += gridDim.x * blockDim.x)
        out[i] = src[i];
}

// ---------------- host launcher ----------------

extern "C" void kernel_launch(void* const* d_in, const int* in_sizes, int n_in,
                              void* d_out, int out_size) {
    const float* af    = (const float*)d_in[0];
    const int*   batch = (const int*)d_in[3];
    const int*   eidx  = (const int*)d_in[4];
    const int*   bei   = (const int*)d_in[5];
    const float* iw1 = (const float*)d_in[6];
    const float* ib1 = (const float*)d_in[7];
    const float* iw2 = (const float*)d_in[8];
    const float* ib2 = (const float*)d_in[9];
    const float* emb = (const float*)d_in[10];
    const float* mw1 = (const float*)d_in[11];
    const float* mb1 = (const float*)d_in[12];
    const float* mw2 = (const float*)d_in[13];
    const float* mb2 = (const float*)d_in[14];
    const float* uw1 = (const float*)d_in[15];
    const float* ub1 = (const float*)d_in[16];
    const float* uw2 = (const float*)d_in[17];
    const float* ub2 = (const float*)d_in[18];

    int E  = in_sizes[4] / 2;
    int BE = in_sizes[5] / 2;
    int G  = out_size / 64 - E;

    const int SH_INIT = (16384 + 4096 + 128 + 2048) * 4;  // 90624
    const int SH_MSG  = (12288 + 4096 + 128 + 2048) * 4;  // 74240
    const int SH_UPD  = ( 8192 + 4096 + 128 + 2048) * 4;  // 57856
    cudaFuncSetAttribute(k_init, cudaFuncAttributeMaxDynamicSharedMemorySize, SH_INIT);
    cudaFuncSetAttribute(k_msg,  cudaFuncAttributeMaxDynamicSharedMemorySize, SH_MSG);
    cudaFuncSetAttribute(k_upd,  cudaFuncAttributeMaxDynamicSharedMemorySize, SH_UPD);

    int gE64   = (E + 63) / 64;
    int gBE64  = (BE + 63) / 64;
    int gE256  = (E + 255) / 256;
    int gBE256 = (BE + 255) / 256;

    k_zero_small<<<gE256, 256>>>(E);
    k_init<<<gE64, 256, SH_INIT>>>(af, eidx, iw1, ib1, iw2, ib2, E);
    k_deg<<<gBE256, 256>>>(bei, BE);

    for (int l = 0; l < 2; l++) {
        k_zero_aggr<<<1024, 256>>>(E * 64);
        k_msg<<<gBE64, 256, SH_MSG>>>(bei, emb + l * 320,
                                      mw1 + l * 12288, mb1 + l * 64,
                                      mw2 + l * 4096,  mb2 + l * 64, BE);
        k_upd<<<gE64, 256, SH_UPD>>>(uw1 + l * 8192, ub1 + l * 64,
                                     uw2 + l * 4096, ub2 + l * 64, E);
    }

    k_cnt<<<gE256, 256>>>(eidx, batch, E);
    k_pool2<<<(E * 16 + 255) / 256, 256>>>(eidx, batch, E);
    k_fin<<<(G * 64 + 255) / 256, 256>>>((float*)d_out + (size_t)E * 64, G);
    k_copy<<<1024, 256>>>((float4*)d_out, E * 16);
}

// round 4
// speedup vs baseline: 1.1606x; 1.1606x over previous
#include <cuda_runtime.h>

#define EMAX 65536
#define GMAX 64
#define MT   128      // edges per msg/upd CTA
#define MSTR (MT + 4) // 132
#define IT   64       // edges per init CTA
#define ISTR (IT + 4) // 68

__device__ float g_x[(size_t)EMAX * 64];
__device__ float g_aggr[(size_t)EMAX * 64];
__device__ float g_deg[EMAX];
__device__ int   g_bt[EMAX];
__device__ float g_gsum[GMAX * 64];
__device__ float g_gcnt[GMAX];

typedef unsigned long long u64;

__device__ __forceinline__ u64 pack2(float x) {
    u64 r; asm("mov.b64 %0, {%1, %2};" : "=l"(r) : "f"(x), "f"(x)); return r;
}
__device__ __forceinline__ void unpack2(u64 v, float& lo, float& hi) {
    asm("mov.b64 {%0, %1}, %2;" : "=f"(lo), "=f"(hi) : "l"(v));
}
__device__ __forceinline__ float gethalf(u64 v, int which) {
    float lo, hi; unpack2(v, lo, hi); return which ? hi : lo;
}
__device__ __forceinline__ u64 ffma2(u64 a, u64 b, u64 c) {
    u64 d; asm("fma.rn.f32x2 %0, %1, %2, %3;" : "=l"(d) : "l"(a), "l"(b), "l"(c)); return d;
}
__device__ __forceinline__ float silu_f(float v) {
    return __fdividef(v, 1.f + __expf(-v));
}

__device__ __forceinline__ void cpys(float* dst, const float* __restrict__ src, int n) {
    const float4* s4 = (const float4*)src; float4* d4 = (float4*)dst;
    for (int i = threadIdx.x; i < (n >> 2); i += blockDim.x) d4[i] = s4[i];
}

// Register-blocked GEMM from SMEM. acc[ep][c]: edge-pairs {eg*4+2ep, eg*4+2ep+1} x cols cg*4+c.
template<int KK, int STR>
__device__ __forceinline__ void gemm_acc(const float* As, const float* Ws,
                                         int eg, int cg, u64 acc[2][4]) {
    const float* ap = As + eg * 4;
    const float* wp = Ws + cg * 4;
    #pragma unroll 4
    for (int k = 0; k < KK; k++) {
        ulonglong2 av = *(const ulonglong2*)(ap + k * STR);
        float4 wv = *(const float4*)(wp + k * 64);
        u64 w0 = pack2(wv.x), w1 = pack2(wv.y), w2 = pack2(wv.z), w3 = pack2(wv.w);
        acc[0][0] = ffma2(av.x, w0, acc[0][0]); acc[0][1] = ffma2(av.x, w1, acc[0][1]);
        acc[0][2] = ffma2(av.x, w2, acc[0][2]); acc[0][3] = ffma2(av.x, w3, acc[0][3]);
        acc[1][0] = ffma2(av.y, w0, acc[1][0]); acc[1][1] = ffma2(av.y, w1, acc[1][1]);
        acc[1][2] = ffma2(av.y, w2, acc[1][2]); acc[1][3] = ffma2(av.y, w3, acc[1][3]);
    }
}

__device__ __forceinline__ void bias_init(const float* __restrict__ b, int cg, u64 acc[2][4]) {
    float4 bv = *(const float4*)(b + cg * 4);
    acc[0][0] = acc[1][0] = pack2(bv.x);
    acc[0][1] = acc[1][1] = pack2(bv.y);
    acc[0][2] = acc[1][2] = pack2(bv.z);
    acc[0][3] = acc[1][3] = pack2(bv.w);
}

template<int STR>
__device__ __forceinline__ void silu_store(const u64 acc[2][4], float* Hs, int eg, int cg) {
    #pragma unroll
    for (int c = 0; c < 4; c++) {
        float x0, x1, x2, x3;
        unpack2(acc[0][c], x0, x1); unpack2(acc[1][c], x2, x3);
        float4 hv = make_float4(silu_f(x0), silu_f(x1), silu_f(x2), silu_f(x3));
        *(float4*)(Hs + (cg * 4 + c) * STR + eg * 4) = hv;
    }
}

// ---------------- kernels ----------------

__global__ void k_zero(int E) {
    int stride = gridDim.x * blockDim.x;
    for (int i = blockIdx.x * blockDim.x + threadIdx.x; i < E * 64; i += stride)
        g_aggr[i] = 0.f;
    int i = blockIdx.x * blockDim.x + threadIdx.x;
    if (i < E) g_deg[i] = 0.f;
    if (i < GMAX * 64) g_gsum[i] = 0.f;
    if (i < GMAX) g_gcnt[i] = 0.f;
}

__global__ void k_deg(const int* __restrict__ bei, int BE) {
    int b = blockIdx.x * blockDim.x + threadIdx.x;
    if (b < BE) atomicAdd(&g_deg[bei[BE + b]], 1.f);
}

// bond_init: 64 edges/CTA, 256 threads. A = [hi(128); hj(128)] k-major.
extern "C" __global__ void __launch_bounds__(256, 1)
k_init(const float* __restrict__ af, const int* __restrict__ eidx,
       const float* __restrict__ iw1, const float* __restrict__ ib1,
       const float* __restrict__ iw2, const float* __restrict__ ib2, int E) {
    extern __shared__ float sm[];
    float* W1s = sm;                  // 16384
    float* W2s = sm + 16384;          // 4096
    float* As  = sm + 20480;          // 256*68 = 17408
    float* Hs  = sm + 20480 + 17408;  // 64*68 = 4352
    cpys(W1s, iw1, 16384); cpys(W2s, iw2, 4096);

    int tid = threadIdx.x;
    int e_loc = tid >> 2, p = tid & 3;
    int e = blockIdx.x * IT + e_loc;
    int ec = (e < E) ? e : 0;
    int r = eidx[ec], c = eidx[E + ec];
    const float* hi = af + (size_t)r * 128;
    const float* hj = af + (size_t)c * 128;
    #pragma unroll
    for (int i = 0; i < 8; i++) {          // hi: f4 j = p+4i, j in 0..31
        int j = p + 4 * i;
        float4 v = ((const float4*)hi)[j];
        int k = 4 * j;
        As[(k + 0) * ISTR + e_loc] = v.x; As[(k + 1) * ISTR + e_loc] = v.y;
        As[(k + 2) * ISTR + e_loc] = v.z; As[(k + 3) * ISTR + e_loc] = v.w;
    }
    #pragma unroll
    for (int i = 0; i < 8; i++) {          // hj at k offset 128
        int j = p + 4 * i;
        float4 v = ((const float4*)hj)[j];
        int k = 128 + 4 * j;
        As[(k + 0) * ISTR + e_loc] = v.x; As[(k + 1) * ISTR + e_loc] = v.y;
        As[(k + 2) * ISTR + e_loc] = v.z; As[(k + 3) * ISTR + e_loc] = v.w;
    }
    __syncthreads();

    // cosine similarity from SMEM: 4 threads/edge split 128 dims
    {
        float dot = 0.f, ni = 0.f, nj = 0.f;
        #pragma unroll 8
        for (int t = 0; t < 32; t++) {
            int k = p * 32 + t;
            float a = As[k * ISTR + e_loc];
            float b = As[(128 + k) * ISTR + e_loc];
            dot += a * b; ni += a * a; nj += b * b;
        }
        dot += __shfl_xor_sync(~0u, dot, 1); dot += __shfl_xor_sync(~0u, dot, 2);
        ni  += __shfl_xor_sync(~0u, ni, 1);  ni  += __shfl_xor_sync(~0u, ni, 2);
        nj  += __shfl_xor_sync(~0u, nj, 1);  nj  += __shfl_xor_sync(~0u, nj, 2);
        if (p == 0 && e < E) {
            float a = fmaxf(sqrtf(ni), 1e-8f), b = fmaxf(sqrtf(nj), 1e-8f);
            float sim = dot / (a * b);
            int bt = 0;
            if (sim > 0.8f) bt = 1;
            if (sim > 0.9f) bt = 2;
            if (sim < 0.3f) bt = 3;
            g_bt[e] = bt;
        }
    }

    int eg = tid >> 4, cg = tid & 15;
    u64 a1[2][4]; bias_init(ib1, cg, a1);
    gemm_acc<256, ISTR>(As, W1s, eg, cg, a1);
    silu_store<ISTR>(a1, Hs, eg, cg);
    __syncthreads();
    u64 o[2][4]; bias_init(ib2, cg, o);
    gemm_acc<64, ISTR>(Hs, W2s, eg, cg, o);

    int ebase = blockIdx.x * IT + eg * 4;
    #pragma unroll
    for (int j = 0; j < 4; j++) {
        if (ebase + j < E) {
            float4 v;
            v.x = gethalf(o[j >> 1][0], j & 1); v.y = gethalf(o[j >> 1][1], j & 1);
            v.z = gethalf(o[j >> 1][2], j & 1); v.w = gethalf(o[j >> 1][3], j & 1);
            *(float4*)(g_x + (size_t)(ebase + j) * 64 + cg * 4) = v;
        }
    }
}

// message MLP: 128 edges/CTA, 512 threads. A = [x[dst]; x[src]; te[dst]] k-major.
extern "C" __global__ void __launch_bounds__(512, 1)
k_msg(const int* __restrict__ bei, const float* __restrict__ embl,
      const float* __restrict__ mw1, const float* __restrict__ mb1,
      const float* __restrict__ mw2, const float* __restrict__ mb2, int BE) {
    extern __shared__ float sm[];
    float* W1s = sm;                   // 12288
    float* W2s = sm + 12288;           // 4096
    float* As  = sm + 16384;           // 192*132 = 25344
    float* Hs  = sm + 16384 + 25344;   // 64*132 = 8448
    int*   ds  = (int*)(Hs + 8448);    // 128
    cpys(W1s, mw1, 12288); cpys(W2s, mw2, 4096);

    int tid = threadIdx.x;
    int e_loc = tid >> 2, p = tid & 3;
    int e = blockIdx.x * MT + e_loc;
    int ec = (e < BE) ? e : 0;
    int s = bei[ec], d = bei[BE + ec];
    if (p == 0) ds[e_loc] = d;
    const float* r0 = g_x + (size_t)d * 64;
    const float* r1 = g_x + (size_t)s * 64;
    const float* r2 = embl + g_bt[d] * 64;
    #pragma unroll
    for (int i = 0; i < 4; i++) {
        int j = p + 4 * i;                       // 0..15
        float4 v = ((const float4*)r0)[j];
        int k = 4 * j;
        As[(k + 0) * MSTR + e_loc] = v.x; As[(k + 1) * MSTR + e_loc] = v.y;
        As[(k + 2) * MSTR + e_loc] = v.z; As[(k + 3) * MSTR + e_loc] = v.w;
    }
    #pragma unroll
    for (int i = 0; i < 4; i++) {
        int j = p + 4 * i;
        float4 v = ((const float4*)r1)[j];
        int k = 64 + 4 * j;
        As[(k + 0) * MSTR + e_loc] = v.x; As[(k + 1) * MSTR + e_loc] = v.y;
        As[(k + 2) * MSTR + e_loc] = v.z; As[(k + 3) * MSTR + e_loc] = v.w;
    }
    #pragma unroll
    for (int i = 0; i < 4; i++) {
        int j = p + 4 * i;
        float4 v = ((const float4*)r2)[j];
        int k = 128 + 4 * j;
        As[(k + 0) * MSTR + e_loc] = v.x; As[(k + 1) * MSTR + e_loc] = v.y;
        As[(k + 2) * MSTR + e_loc] = v.z; As[(k + 3) * MSTR + e_loc] = v.w;
    }
    __syncthreads();

    int eg = tid >> 4, cg = tid & 15;
    u64 a1[2][4]; bias_init(mb1, cg, a1);
    gemm_acc<192, MSTR>(As, W1s, eg, cg, a1);
    silu_store<MSTR>(a1, Hs, eg, cg);
    __syncthreads();
    u64 o[2][4]; bias_init(mb2, cg, o);
    gemm_acc<64, MSTR>(Hs, W2s, eg, cg, o);

    int ebase = blockIdx.x * MT + eg * 4;
    #pragma unroll
    for (int j = 0; j < 4; j++) {
        if (ebase + j < BE) {
            int dd = ds[eg * 4 + j];
            float x0 = gethalf(o[j >> 1][0], j & 1), x1 = gethalf(o[j >> 1][1], j & 1);
            float x2 = gethalf(o[j >> 1][2], j & 1), x3 = gethalf(o[j >> 1][3], j & 1);
            asm volatile("red.global.add.v4.f32 [%0], {%1,%2,%3,%4};"
                         :: "l"(g_aggr + (size_t)dd * 64 + cg * 4),
                            "f"(x0), "f"(x1), "f"(x2), "f"(x3) : "memory");
        }
    }
}

// update MLP: 128 edges/CTA, 512 threads. A = [aggr/deg (64); x (64)].
// Gather also re-zeroes aggr for the next layer (guarded by e<E).
extern "C" __global__ void __launch_bounds__(512, 1)
k_upd(const float* __restrict__ uw1, const float* __restrict__ ub1,
      const float* __restrict__ uw2, const float* __restrict__ ub2, int E) {
    extern __shared__ float sm[];
    float* W1s = sm;                  // 8192
    float* W2s = sm + 8192;           // 4096
    float* As  = sm + 12288;          // 128*132 = 16896
    float* Hs  = sm + 12288 + 16896;  // 8448
    cpys(W1s, uw1, 8192); cpys(W2s, uw2, 4096);

    int tid = threadIdx.x;
    int e_loc = tid >> 2, p = tid & 3;
    int e = blockIdx.x * MT + e_loc;
    int ec = (e < E) ? e : 0;
    float rdiv = 1.f / fmaxf(g_deg[ec], 1.f);
    float* arow = g_aggr + (size_t)ec * 64;
    const float* xrow = g_x + (size_t)ec * 64;
    #pragma unroll
    for (int i = 0; i < 4; i++) {
        int j = p + 4 * i;                        // 0..15: aggr
        float4 v = ((const float4*)arow)[j];
        int k = 4 * j;
        As[(k + 0) * MSTR + e_loc] = v.x * rdiv; As[(k + 1) * MSTR + e_loc] = v.y * rdiv;
        As[(k + 2) * MSTR + e_loc] = v.z * rdiv; As[(k + 3) * MSTR + e_loc] = v.w * rdiv;
        if (e < E) ((float4*)arow)[j] = make_float4(0.f, 0.f, 0.f, 0.f);
    }
    #pragma unroll
    for (int i = 0; i < 4; i++) {
        int j = p + 4 * i;                        // x at k offset 64
        float4 v = ((const float4*)xrow)[j];
        int k = 64 + 4 * j;
        As[(k + 0) * MSTR + e_loc] = v.x; As[(k + 1) * MSTR + e_loc] = v.y;
        As[(k + 2) * MSTR + e_loc] = v.z; As[(k + 3) * MSTR + e_loc] = v.w;
    }
    __syncthreads();

    int eg = tid >> 4, cg = tid & 15;
    u64 a1[2][4]; bias_init(ub1, cg, a1);
    gemm_acc<128, MSTR>(As, W1s, eg, cg, a1);
    silu_store<MSTR>(a1, Hs, eg, cg);
    __syncthreads();
    u64 o[2][4]; bias_init(ub2, cg, o);
    gemm_acc<64, MSTR>(Hs, W2s, eg, cg, o);

    int ebase = blockIdx.x * MT + eg * 4;
    #pragma unroll
    for (int j = 0; j < 4; j++) {
        if (ebase + j < E) {
            float* xp = g_x + (size_t)(ebase + j) * 64 + cg * 4;
            float4 xv = *(float4*)xp;
            xv.x += gethalf(o[j >> 1][0], j & 1); xv.y += gethalf(o[j >> 1][1], j & 1);
            xv.z += gethalf(o[j >> 1][2], j & 1); xv.w += gethalf(o[j >> 1][3], j & 1);
            *(float4*)xp = xv;
        }
    }
}

__global__ void k_cnt(const int* __restrict__ eidx, const int* __restrict__ batch, int E) {
    int e = blockIdx.x * blockDim.x + threadIdx.x;
    if (e < E) atomicAdd(&g_gcnt[batch[eidx[e]]], 1.f);
}

__global__ void k_pool2(const int* __restrict__ eidx, const int* __restrict__ batch, int E) {
    int i = blockIdx.x * blockDim.x + threadIdx.x;
    if (i >= E * 16) return;
    int e = i >> 4, cc = i & 15;
    int gph = batch[eidx[e]];
    float4 v = ((const float4*)g_x)[(size_t)e * 16 + cc];
    float* dst = g_gsum + gph * 64 + cc * 4;
    asm volatile("red.global.add.v4.f32 [%0], {%1,%2,%3,%4};"
                 :: "l"(dst), "f"(v.x), "f"(v.y), "f"(v.z), "f"(v.w) : "memory");
}

__global__ void k_fin(float* __restrict__ out, int G) {
    int i = blockIdx.x * blockDim.x + threadIdx.x;
    if (i < G * 64) out[i] = g_gsum[i] / fmaxf(g_gcnt[i >> 6], 1.f);
}

__global__ void k_copy(float4* __restrict__ out, int n4) {
    const float4* src = (const float4*)g_x;
    for (int i = blockIdx.x * blockDim.x + threadIdx.x; i < n4; i += gridDim.x * blockDim.x)
        out[i] = src[i];
}

// ---------------- host launcher ----------------

extern "C" void kernel_launch(void* const* d_in, const int* in_sizes, int n_in,
                              void* d_out, int out_size) {
    const float* af    = (const float*)d_in[0];
    const int*   batch = (const int*)d_in[3];
    const int*   eidx  = (const int*)d_in[4];
    const int*   bei   = (const int*)d_in[5];
    const float* iw1 = (const float*)d_in[6];
    const float* ib1 = (const float*)d_in[7];
    const float* iw2 = (const float*)d_in[8];
    const float* ib2 = (const float*)d_in[9];
    const float* emb = (const float*)d_in[10];
    const float* mw1 = (const float*)d_in[11];
    const float* mb1 = (const float*)d_in[12];
    const float* mw2 = (const float*)d_in[13];
    const float* mb2 = (const float*)d_in[14];
    const float* uw1 = (const float*)d_in[15];
    const float* ub1 = (const float*)d_in[16];
    const float* uw2 = (const float*)d_in[17];
    const float* ub2 = (const float*)d_in[18];

    int E  = in_sizes[4] / 2;
    int BE = in_sizes[5] / 2;
    int G  = out_size / 64 - E;

    const int SH_INIT = (16384 + 4096 + 256 * ISTR + 64 * ISTR) * 4;            // 169 KB
    const int SH_MSG  = (12288 + 4096 + 192 * MSTR + 64 * MSTR) * 4 + 512;      // ~197 KB
    const int SH_UPD  = (8192 + 4096 + 128 * MSTR + 64 * MSTR) * 4;             // ~147 KB
    cudaFuncSetAttribute(k_init, cudaFuncAttributeMaxDynamicSharedMemorySize, SH_INIT);
    cudaFuncSetAttribute(k_msg,  cudaFuncAttributeMaxDynamicSharedMemorySize, SH_MSG);
    cudaFuncSetAttribute(k_upd,  cudaFuncAttributeMaxDynamicSharedMemorySize, SH_UPD);

    int gI  = (E + IT - 1) / IT;
    int gM  = (BE + MT - 1) / MT;
    int gU  = (E + MT - 1) / MT;
    int gE256  = (E + 255) / 256;
    int gBE256 = (BE + 255) / 256;

    k_zero<<<2048, 256>>>(E);
    k_init<<<gI, 256, SH_INIT>>>(af, eidx, iw1, ib1, iw2, ib2, E);
    k_deg<<<gBE256, 256>>>(bei, BE);

    for (int l = 0; l < 2; l++) {
        k_msg<<<gM, 512, SH_MSG>>>(bei, emb + l * 320,
                                   mw1 + l * 12288, mb1 + l * 64,
                                   mw2 + l * 4096,  mb2 + l * 64, BE);
        k_upd<<<gU, 512, SH_UPD>>>(uw1 + l * 8192, ub1 + l * 64,
                                   uw2 + l * 4096, ub2 + l * 64, E);
    }

    k_cnt<<<gE256, 256>>>(eidx, batch, E);
    k_pool2<<<(E * 16 + 255) / 256, 256>>>(eidx, batch, E);
    k_fin<<<(G * 64 + 255) / 256, 256>>>((float*)d_out + (size_t)E * 64, G);
    k_copy<<<1024, 256>>>((float4*)d_out, E * 16);
}